// round 13
// baseline (speedup 1.0000x reference)
#include <cuda_runtime.h>
#include <math.h>

#define BSZ   256
#define ISIZE 256
#define HSIZE 512
#define BH    (BSZ*HSIZE)
#define BK 16

#define NGATE  128            // 4 gates x 32 tiles (64x64), FULL K per unit
#define NRED   1024           // reduce units: (b, quarter) = 128 rows each
#define GRID1  (NGATE + NRED) // 1152 blocks of 128 thr -> single wave

// Scratch (device globals)
__device__ __align__(16) float g_pre[4*BH];     // gate preactivations
__device__ __align__(16) float g_hredp[4*BH];   // hred partials (4 quarters)
__device__ __align__(16) float g_ei[BH];        // eta*its per (b,k)

// ---------------------------------------------------------------------------
// K1: 1152 blocks x 128 threads, all co-resident in ONE wave.
//  bid [0,128):    gate GEMM blocks (64x64 tile, full K=768) -- FMA work
//                  rides idle issue slots of the 7 streaming blocks per SM.
//  bid [128,1152): reduce blocks (b, quarter): barrier-free, smem-free;
//                  thread c owns f4-column c, sums 128 rows, writes partial.
// ---------------------------------------------------------------------------
__global__ __launch_bounds__(128, 8)
void k1(const float* __restrict__ x, const float* __restrict__ h0,
        const float* __restrict__ hebb,
        const float* __restrict__ x2f, const float* __restrict__ x2i,
        const float* __restrict__ x2o, const float* __restrict__ x2c,
        const float* __restrict__ h2f, const float* __restrict__ h2i,
        const float* __restrict__ h2o, const float* __restrict__ w)
{
    __shared__ __align__(16) float As[BK][68];
    __shared__ __align__(16) float Ws[BK][68];

    int tid = threadIdx.x;
    int bid = blockIdx.x;

    if (bid >= NGATE) {
        // ---------------- reduce block: (b, quarter) -----------------------
        int ru = bid - NGATE;          // 0..1023
        int b = ru >> 2;
        int q = ru & 3;
        int c = tid;                   // f4 column 0..127
        const float4* hb4 = (const float4*)(hebb + (size_t)b * HSIZE * HSIZE)
                            + (size_t)(q * 128) * 128 + c;
        const float* h0p = h0 + b * HSIZE + q * 128;
        float4 acc = make_float4(0.f, 0.f, 0.f, 0.f);
#pragma unroll 8
        for (int i = 0; i < 128; ++i) {
            float sv = __ldg(h0p + i);
            float4 v = hb4[(size_t)i * 128];
            acc.x = fmaf(sv, v.x, acc.x);
            acc.y = fmaf(sv, v.y, acc.y);
            acc.z = fmaf(sv, v.z, acc.z);
            acc.w = fmaf(sv, v.w, acc.w);
        }
        ((float4*)(g_hredp + (size_t)q * BH + b * HSIZE))[c] = acc;
        return;
    }

    // ---------------- gate GEMM block: 64x64 tile, full K ------------------
    int gate = bid >> 5;
    int ct = bid & 31;
    int bn0 = (ct & 7) * 64;           // k (output col) offset
    int bm0 = (ct >> 3) * 64;          // b (output row) offset
    const float* xw = (gate == 0) ? x2f : (gate == 1) ? x2i
                    : (gate == 2) ? x2o : x2c;
    const float* hw = (gate == 0) ? h2f : (gate == 1) ? h2i
                    : (gate == 2) ? h2o : w;

    int tx = tid & 15;                 // 4 cols each
    int ty = tid >> 4;                 // 0..7, 8 rows each
    float acc[8][4] = {};

    for (int phase = 0; phase < 2; ++phase) {
        const float* A = phase ? h0 : x;
        int K = phase ? HSIZE : ISIZE;
        const float* W = phase ? hw : xw;
        bool trans = (phase == 1) && (gate == 3);   // w is [h,k]

        for (int k0 = 0; k0 < K; k0 += BK) {
#pragma unroll
            for (int l = 0; l < 8; l++) {
                int e = tid + l * 128; int rr = e >> 4; int cc = e & 15;
                As[cc][rr] = A[(size_t)(bm0 + rr) * K + k0 + cc];
            }
            if (trans) {
#pragma unroll
                for (int l = 0; l < 8; l++) {
                    int e = tid + l * 128; int rr = e & 63; int cc = e >> 6;
                    Ws[cc][rr] = W[(size_t)(k0 + cc) * HSIZE + bn0 + rr];
                }
            } else {
#pragma unroll
                for (int l = 0; l < 8; l++) {
                    int e = tid + l * 128; int rr = e >> 4; int cc = e & 15;
                    Ws[cc][rr] = W[(size_t)(bn0 + rr) * K + k0 + cc];
                }
            }
            __syncthreads();
#pragma unroll
            for (int kb = 0; kb < BK; kb++) {
                float4 ra0 = *(const float4*)&As[kb][ty * 8];
                float4 ra1 = *(const float4*)&As[kb][ty * 8 + 4];
                float4 rb = *(const float4*)&Ws[kb][tx * 4];
                float a[8] = {ra0.x, ra0.y, ra0.z, ra0.w,
                              ra1.x, ra1.y, ra1.z, ra1.w};
                float bv[4] = {rb.x, rb.y, rb.z, rb.w};
#pragma unroll
                for (int i = 0; i < 8; i++)
#pragma unroll
                    for (int j = 0; j < 4; j++)
                        acc[i][j] = fmaf(a[i], bv[j], acc[i][j]);
            }
            __syncthreads();
        }
    }
    float* outb = g_pre + (size_t)gate * BH;
#pragma unroll
    for (int i = 0; i < 8; i++) {
        int bb = bm0 + ty * 8 + i;
#pragma unroll
        for (int j = 0; j < 4; j++)
            outb[(size_t)bb * HSIZE + bn0 + tx * 4 + j] = acc[i][j];
    }
}

// ---------------------------------------------------------------------------
// K2: per-batch cell/hactiv + modulation scalar + ei = (m*mfw+mfb)*its.
// ---------------------------------------------------------------------------
__global__ __launch_bounds__(HSIZE)
void k2(const float* __restrict__ c0, const float* __restrict__ alpha,
        const float* __restrict__ x2f_b, const float* __restrict__ h2f_b,
        const float* __restrict__ x2i_b, const float* __restrict__ h2i_b,
        const float* __restrict__ x2o_b, const float* __restrict__ h2o_b,
        const float* __restrict__ x2c_b,
        const float* __restrict__ h2mod_w, const float* __restrict__ h2mod_b,
        const float* __restrict__ mfw, const float* __restrict__ mfb,
        float* __restrict__ out_hact, float* __restrict__ out_cell)
{
    __shared__ float sred[16];
    __shared__ float smv;
    int b = blockIdx.x;
    int k = threadIdx.x;
    int idx = b * HSIZE + k;

    float hred = g_hredp[idx] + g_hredp[BH + idx]
               + g_hredp[2 * BH + idx] + g_hredp[3 * BH + idx];

    float pf = g_pre[idx]          + x2f_b[k] + h2f_b[k];
    float pi = g_pre[BH + idx]     + x2i_b[k] + h2i_b[k];
    float po = g_pre[2 * BH + idx] + x2o_b[k] + h2o_b[k];
    float pc = g_pre[3 * BH + idx] + x2c_b[k] + alpha[k] * hred;
    float fgt = 1.f / (1.f + expf(-pf));
    float ipt = 1.f / (1.f + expf(-pi));
    float opt = 1.f / (1.f + expf(-po));
    float its = tanhf(pc);
    float cell = fgt * c0[idx] + ipt * its;
    float hact = opt * tanhf(cell);
    out_cell[idx] = cell;
    out_hact[idx] = hact;

    float mv = hact * h2mod_w[k];
#pragma unroll
    for (int o = 16; o > 0; o >>= 1) mv += __shfl_down_sync(0xffffffffu, mv, o);
    if ((k & 31) == 0) sred[k >> 5] = mv;
    __syncthreads();
    if (k == 0) {
        float s = 0.f;
#pragma unroll
        for (int i = 0; i < 16; i++) s += sred[i];
        smv = tanhf(s + h2mod_b[0]);
    }
    __syncthreads();
    g_ei[idx] = fmaf(smv, mfw[k], mfb[k]) * its;
}

// ---------------------------------------------------------------------------
// K3: hebb_new[b,h,k] = clip(hebb + h0[b,h]*ei[b,k], -2, 2). Pure streaming.
// ---------------------------------------------------------------------------
__global__ __launch_bounds__(256)
void k3(const float4* __restrict__ hebb4, const float* __restrict__ h0,
        float4* __restrict__ out4)
{
    const float4* ei4 = reinterpret_cast<const float4*>(g_ei);
    int base = blockIdx.x * 1024 + threadIdx.x;
#pragma unroll
    for (int j = 0; j < 4; j++) {
        int idx = base + j * 256;
        int k4 = idx & 127;
        int bh = idx >> 7;
        int b = bh >> 9;
        float s = h0[bh];
        float4 e = ei4[(b << 7) + k4];
        float4 hv = hebb4[idx];
        float v;
        v = fmaf(s, e.x, hv.x); hv.x = fminf(fmaxf(v, -2.f), 2.f);
        v = fmaf(s, e.y, hv.y); hv.y = fminf(fmaxf(v, -2.f), 2.f);
        v = fmaf(s, e.z, hv.z); hv.z = fminf(fmaxf(v, -2.f), 2.f);
        v = fmaf(s, e.w, hv.w); hv.w = fminf(fmaxf(v, -2.f), 2.f);
        out4[idx] = hv;
    }
}

// ---------------------------------------------------------------------------
extern "C" void kernel_launch(void* const* d_in, const int* in_sizes, int n_in,
                              void* d_out, int out_size)
{
    const float* inputs  = (const float*)d_in[0];
    const float* h0      = (const float*)d_in[1];
    const float* c0      = (const float*)d_in[2];
    const float* hebb    = (const float*)d_in[3];
    const float* w       = (const float*)d_in[4];
    const float* alpha   = (const float*)d_in[5];
    const float* h2f_w   = (const float*)d_in[6];
    const float* h2f_b   = (const float*)d_in[7];
    const float* h2i_w   = (const float*)d_in[8];
    const float* h2i_b   = (const float*)d_in[9];
    const float* h2o_w   = (const float*)d_in[10];
    const float* h2o_b   = (const float*)d_in[11];
    const float* x2f_w   = (const float*)d_in[12];
    const float* x2f_b   = (const float*)d_in[13];
    const float* x2i_w   = (const float*)d_in[14];
    const float* x2i_b   = (const float*)d_in[15];
    const float* x2o_w   = (const float*)d_in[16];
    const float* x2o_b   = (const float*)d_in[17];
    const float* x2c_w   = (const float*)d_in[18];
    const float* x2c_b   = (const float*)d_in[19];
    const float* h2mod_w = (const float*)d_in[20];
    const float* h2mod_b = (const float*)d_in[21];
    const float* mfw     = (const float*)d_in[22];
    const float* mfb     = (const float*)d_in[23];

    float* out       = (float*)d_out;
    float* out_hact  = out;              // [B,H]
    float* out_cell  = out + BH;         // [B,H]
    float* out_hebb  = out + 2 * BH;     // [B,H,H]

    // K1: single-wave mix of gate blocks + streaming reduce blocks
    k1<<<GRID1, 128>>>(inputs, h0, hebb,
                       x2f_w, x2i_w, x2o_w, x2c_w,
                       h2f_w, h2i_w, h2o_w, w);

    // K2: cell / hactiv / m / ei
    k2<<<BSZ, HSIZE>>>(c0, alpha, x2f_b, h2f_b, x2i_b, h2i_b, x2o_b, h2o_b,
                       x2c_b, h2mod_w, h2mod_b, mfw, mfb, out_hact, out_cell);

    // K3: hebb update (268MB R + 268MB W streaming)
    int nblk = (BSZ * HSIZE * HSIZE / 4) / 1024;   // 8192
    k3<<<nblk, 256>>>((const float4*)hebb, h0, (float4*)out_hebb);
}

// round 14
// speedup vs baseline: 1.1611x; 1.1611x over previous
#include <cuda_runtime.h>
#include <mma.h>
#include <math.h>

using namespace nvcuda;

#define BSZ   256
#define ISIZE 256
#define HSIZE 512
#define BH    (BSZ*HSIZE)

// Scratch (device globals)
__device__ __align__(16) float g_pre[4*BH];     // gate preactivations
__device__ __align__(16) float g_hredp[8*BH];   // hred partials (4 quarters x 2 groups)
__device__ __align__(16) float g_ei[BH];        // eta*its per (b,k)

// ---------------------------------------------------------------------------
// split v into hi (tf32-truncated, exactly representable) + lo (exact residue)
// ---------------------------------------------------------------------------
__device__ __forceinline__ void cvt2(float v, float& hi, float& lo)
{
    hi = __uint_as_float(__float_as_uint(v) & 0xffffe000u);
    lo = v - hi;
}

// ---------------------------------------------------------------------------
// KGATES: tf32 tensor-core gate GEMM, error-compensated (3 mma per step).
// pre[gate][b][k] = sum_j Acat[b][j] * Wcat[gate][k][j]
//   Acat[b][j] = x[b][j] (j<256) else h0[b][j-256]
//   Wcat[g][k][j] = xw_g[k][j] (j<256) else (g<3 ? hw_g[k][j-256] : w[j-256][k])
// Grid (8,4,4): 64x64 tile per block, K=768 in steps of 32. 256 threads.
// ---------------------------------------------------------------------------
__global__ __launch_bounds__(256)
void kgates(const float* __restrict__ x, const float* __restrict__ h0,
            const float* __restrict__ x2f, const float* __restrict__ x2i,
            const float* __restrict__ x2o, const float* __restrict__ x2c,
            const float* __restrict__ h2f, const float* __restrict__ h2i,
            const float* __restrict__ h2o, const float* __restrict__ w)
{
    __shared__ __align__(16) float sAhi[64][40], sAlo[64][40];
    __shared__ __align__(16) float sBhi[64][40], sBlo[64][40];

    int tid = threadIdx.x;
    int gate = blockIdx.z;
    int bn0 = blockIdx.x * 64;         // output k offset
    int bm0 = blockIdx.y * 64;         // batch row offset

    const float* xw = (gate == 0) ? x2f : (gate == 1) ? x2i
                    : (gate == 2) ? x2o : x2c;
    const float* hw = (gate == 0) ? h2f : (gate == 1) ? h2i
                    : (gate == 2) ? h2o : w;

    int wid = tid >> 5;
    int wr = wid & 3;                  // 16-row fragment index
    int wc = wid >> 2;                 // 0..1: 32-col half

    wmma::fragment<wmma::accumulator, 16, 16, 8, float> acc[2];
    wmma::fill_fragment(acc[0], 0.0f);
    wmma::fill_fragment(acc[1], 0.0f);

    wmma::fragment<wmma::matrix_a, 16, 16, 8, wmma::precision::tf32,
                   wmma::row_major> ahi, alo;
    wmma::fragment<wmma::matrix_b, 16, 16, 8, wmma::precision::tf32,
                   wmma::col_major> bhi, blo;

    for (int k0 = 0; k0 < 768; k0 += 32) {
        // ---- stage A tile (64 rows x 32 cols), float4 + hi/lo split -------
#pragma unroll
        for (int l = 0; l < 2; l++) {
            int e4 = tid + l * 256;
            int row = e4 >> 3;
            int c4 = (e4 & 7) * 4;
            int col = k0 + c4;
            const float* src = (col < 256)
                ? (x  + (size_t)(bm0 + row) * ISIZE + col)
                : (h0 + (size_t)(bm0 + row) * HSIZE + col - 256);
            float4 v = *(const float4*)src;
            float hi, lo;
            cvt2(v.x, hi, lo); sAhi[row][c4    ] = hi; sAlo[row][c4    ] = lo;
            cvt2(v.y, hi, lo); sAhi[row][c4 + 1] = hi; sAlo[row][c4 + 1] = lo;
            cvt2(v.z, hi, lo); sAhi[row][c4 + 2] = hi; sAlo[row][c4 + 2] = lo;
            cvt2(v.w, hi, lo); sAhi[row][c4 + 3] = hi; sAlo[row][c4 + 3] = lo;
        }
        // ---- stage B tile (64 k-rows x 32 j-cols) -------------------------
        bool trans = (gate == 3) && (k0 >= 256);   // w is [h,k]
        if (!trans) {
#pragma unroll
            for (int l = 0; l < 2; l++) {
                int e4 = tid + l * 256;
                int row = e4 >> 3;
                int c4 = (e4 & 7) * 4;
                int col = k0 + c4;
                const float* src = (col < 256)
                    ? (xw + (size_t)(bn0 + row) * ISIZE + col)
                    : (hw + (size_t)(bn0 + row) * HSIZE + col - 256);
                float4 v = *(const float4*)src;
                float hi, lo;
                cvt2(v.x, hi, lo); sBhi[row][c4    ] = hi; sBlo[row][c4    ] = lo;
                cvt2(v.y, hi, lo); sBhi[row][c4 + 1] = hi; sBlo[row][c4 + 1] = lo;
                cvt2(v.z, hi, lo); sBhi[row][c4 + 2] = hi; sBlo[row][c4 + 2] = lo;
                cvt2(v.w, hi, lo); sBhi[row][c4 + 3] = hi; sBlo[row][c4 + 3] = lo;
            }
        } else {
            // element (n, kk) = w[k0+kk-256][bn0+n]; n fast -> coalesced
#pragma unroll
            for (int l = 0; l < 8; l++) {
                int e = tid + l * 256;
                int n = e & 63;
                int kk = e >> 6;
                float v = w[(size_t)(k0 + kk - 256) * HSIZE + bn0 + n];
                float hi, lo;
                cvt2(v, hi, lo);
                sBhi[n][kk] = hi;
                sBlo[n][kk] = lo;
            }
        }
        __syncthreads();

        // ---- tensor math: 4 k-subs of 8 -----------------------------------
#pragma unroll
        for (int ks = 0; ks < 4; ks++) {
            wmma::load_matrix_sync(ahi, &sAhi[wr * 16][ks * 8], 40);
            wmma::load_matrix_sync(alo, &sAlo[wr * 16][ks * 8], 40);
#pragma unroll
            for (int j = 0; j < 2; j++) {
                int n0 = wc * 32 + j * 16;
                wmma::load_matrix_sync(bhi, &sBhi[n0][ks * 8], 40);
                wmma::load_matrix_sync(blo, &sBlo[n0][ks * 8], 40);
                wmma::mma_sync(acc[j], ahi, bhi, acc[j]);
                wmma::mma_sync(acc[j], ahi, blo, acc[j]);
                wmma::mma_sync(acc[j], alo, bhi, acc[j]);
            }
        }
        __syncthreads();
    }

    float* outb = g_pre + (size_t)gate * BH;
#pragma unroll
    for (int j = 0; j < 2; j++) {
        wmma::store_matrix_sync(outb + (size_t)(bm0 + wr * 16) * HSIZE
                                     + bn0 + wc * 32 + j * 16,
                                acc[j], HSIZE, wmma::mem_row_major);
    }
}

// ---------------------------------------------------------------------------
// KREDUCE: hred partials. 1024 blocks x 256 thr, one wave, barrier-free.
// Block (b, quarter): rows q*128..q*128+127. Thread: group g (64 rows), col c.
// ---------------------------------------------------------------------------
__global__ __launch_bounds__(256)
void kreduce(const float* __restrict__ h0, const float* __restrict__ hebb)
{
    int b = blockIdx.x >> 2;
    int q = blockIdx.x & 3;
    int g = threadIdx.x >> 7;          // 0..1 (64 rows each)
    int c = threadIdx.x & 127;         // f4 column
    int hbase = q * 128 + g * 64;
    const float4* hb4 = (const float4*)(hebb + (size_t)b * HSIZE * HSIZE)
                        + (size_t)hbase * 128 + c;
    const float* h0p = h0 + b * HSIZE + hbase;
    float4 acc = make_float4(0.f, 0.f, 0.f, 0.f);
#pragma unroll 8
    for (int i = 0; i < 64; ++i) {
        float sv = __ldg(h0p + i);
        float4 v = hb4[(size_t)i * 128];
        acc.x = fmaf(sv, v.x, acc.x);
        acc.y = fmaf(sv, v.y, acc.y);
        acc.z = fmaf(sv, v.z, acc.z);
        acc.w = fmaf(sv, v.w, acc.w);
    }
    int p = q * 2 + g;
    ((float4*)(g_hredp + (size_t)p * BH + b * HSIZE))[c] = acc;
}

// ---------------------------------------------------------------------------
// K2: per-batch cell/hactiv + modulation scalar + ei = (m*mfw+mfb)*its.
// ---------------------------------------------------------------------------
__global__ __launch_bounds__(HSIZE)
void k2(const float* __restrict__ c0, const float* __restrict__ alpha,
        const float* __restrict__ x2f_b, const float* __restrict__ h2f_b,
        const float* __restrict__ x2i_b, const float* __restrict__ h2i_b,
        const float* __restrict__ x2o_b, const float* __restrict__ h2o_b,
        const float* __restrict__ x2c_b,
        const float* __restrict__ h2mod_w, const float* __restrict__ h2mod_b,
        const float* __restrict__ mfw, const float* __restrict__ mfb,
        float* __restrict__ out_hact, float* __restrict__ out_cell)
{
    __shared__ float sred[16];
    __shared__ float smv;
    int b = blockIdx.x;
    int k = threadIdx.x;
    int idx = b * HSIZE + k;

    float hred = 0.f;
#pragma unroll
    for (int p = 0; p < 8; p++) hred += g_hredp[(size_t)p * BH + idx];

    float pf = g_pre[idx]          + x2f_b[k] + h2f_b[k];
    float pi = g_pre[BH + idx]     + x2i_b[k] + h2i_b[k];
    float po = g_pre[2 * BH + idx] + x2o_b[k] + h2o_b[k];
    float pc = g_pre[3 * BH + idx] + x2c_b[k] + alpha[k] * hred;
    float fgt = 1.f / (1.f + expf(-pf));
    float ipt = 1.f / (1.f + expf(-pi));
    float opt = 1.f / (1.f + expf(-po));
    float its = tanhf(pc);
    float cell = fgt * c0[idx] + ipt * its;
    float hact = opt * tanhf(cell);
    out_cell[idx] = cell;
    out_hact[idx] = hact;

    float mv = hact * h2mod_w[k];
#pragma unroll
    for (int o = 16; o > 0; o >>= 1) mv += __shfl_down_sync(0xffffffffu, mv, o);
    if ((k & 31) == 0) sred[k >> 5] = mv;
    __syncthreads();
    if (k == 0) {
        float s = 0.f;
#pragma unroll
        for (int i = 0; i < 16; i++) s += sred[i];
        smv = tanhf(s + h2mod_b[0]);
    }
    __syncthreads();
    g_ei[idx] = fmaf(smv, mfw[k], mfb[k]) * its;
}

// ---------------------------------------------------------------------------
// K3: hebb_new[b,h,k] = clip(hebb + h0[b,h]*ei[b,k], -2, 2). Pure streaming.
// ---------------------------------------------------------------------------
__global__ __launch_bounds__(256)
void k3(const float4* __restrict__ hebb4, const float* __restrict__ h0,
        float4* __restrict__ out4)
{
    const float4* ei4 = reinterpret_cast<const float4*>(g_ei);
    int base = blockIdx.x * 1024 + threadIdx.x;
#pragma unroll
    for (int j = 0; j < 4; j++) {
        int idx = base + j * 256;
        int k4 = idx & 127;
        int bh = idx >> 7;
        int b = bh >> 9;
        float s = h0[bh];
        float4 e = ei4[(b << 7) + k4];
        float4 hv = hebb4[idx];
        float v;
        v = fmaf(s, e.x, hv.x); hv.x = fminf(fmaxf(v, -2.f), 2.f);
        v = fmaf(s, e.y, hv.y); hv.y = fminf(fmaxf(v, -2.f), 2.f);
        v = fmaf(s, e.z, hv.z); hv.z = fminf(fmaxf(v, -2.f), 2.f);
        v = fmaf(s, e.w, hv.w); hv.w = fminf(fmaxf(v, -2.f), 2.f);
        out4[idx] = hv;
    }
}

// ---------------------------------------------------------------------------
extern "C" void kernel_launch(void* const* d_in, const int* in_sizes, int n_in,
                              void* d_out, int out_size)
{
    const float* inputs  = (const float*)d_in[0];
    const float* h0      = (const float*)d_in[1];
    const float* c0      = (const float*)d_in[2];
    const float* hebb    = (const float*)d_in[3];
    const float* w       = (const float*)d_in[4];
    const float* alpha   = (const float*)d_in[5];
    const float* h2f_w   = (const float*)d_in[6];
    const float* h2f_b   = (const float*)d_in[7];
    const float* h2i_w   = (const float*)d_in[8];
    const float* h2i_b   = (const float*)d_in[9];
    const float* h2o_w   = (const float*)d_in[10];
    const float* h2o_b   = (const float*)d_in[11];
    const float* x2f_w   = (const float*)d_in[12];
    const float* x2f_b   = (const float*)d_in[13];
    const float* x2i_w   = (const float*)d_in[14];
    const float* x2i_b   = (const float*)d_in[15];
    const float* x2o_w   = (const float*)d_in[16];
    const float* x2o_b   = (const float*)d_in[17];
    const float* x2c_w   = (const float*)d_in[18];
    const float* x2c_b   = (const float*)d_in[19];
    const float* h2mod_w = (const float*)d_in[20];
    const float* h2mod_b = (const float*)d_in[21];
    const float* mfw     = (const float*)d_in[22];
    const float* mfb     = (const float*)d_in[23];

    float* out       = (float*)d_out;
    float* out_hact  = out;              // [B,H]
    float* out_cell  = out + BH;         // [B,H]
    float* out_hebb  = out + 2 * BH;     // [B,H,H]

    // 1) tensor-core gate GEMM (tiny: ~2.4 GFLOP on tensor pipe)
    dim3 gg(8, 4, 4);
    kgates<<<gg, 256>>>(inputs, h0, x2f_w, x2i_w, x2o_w, x2c_w,
                        h2f_w, h2i_w, h2o_w, w);

    // 2) streaming hebb reduction (268MB read)
    kreduce<<<BSZ * 4, 256>>>(h0, hebb);

    // 3) cell / hactiv / m / ei
    k2<<<BSZ, HSIZE>>>(c0, alpha, x2f_b, h2f_b, x2i_b, h2i_b, x2o_b, h2o_b,
                       x2c_b, h2mod_w, h2mod_b, mfw, mfb, out_hact, out_cell);

    // 4) hebb update (268MB R + 268MB W streaming)
    int nblk = (BSZ * HSIZE * HSIZE / 4) / 1024;   // 8192
    k3<<<nblk, 256>>>((const float4*)hebb, h0, (float4*)out_hebb);
}

// round 15
// speedup vs baseline: 1.3872x; 1.1948x over previous
#include <cuda_runtime.h>
#include <mma.h>
#include <math.h>

using namespace nvcuda;

#define BSZ   256
#define ISIZE 256
#define HSIZE 512
#define BH    (BSZ*HSIZE)

// Scratch (device globals)
__device__ __align__(16) float g_preA[4*BH];    // gate partials, K 0..383
__device__ __align__(16) float g_preB[4*BH];    // gate partials, K 384..767
__device__ __align__(16) float g_hredp[16*BH];  // hred partials (16 slots)
__device__ __align__(16) float g_ei[BH];        // eta*its per (b,k)

// split v into hi (tf32-truncated) + lo (exact residue)
__device__ __forceinline__ void cvt2(float v, float& hi, float& lo)
{
    hi = __uint_as_float(__float_as_uint(v) & 0xffffe000u);
    lo = v - hi;
}

// ---------------------------------------------------------------------------
// KGATES v3: tf32 tensor GEMM, error-compensated. 256 blocks x 256 thr.
// Grid (8, 8, 4): x = col tile (64), y = {row tile (4) | ksplit (2)}, z = gate.
// Stage RAW fp32 tiles to smem once; hi/lo split in registers.
// pre[g][b][k] = sum_j Acat[b][j] * Wcat[g][k][j], j in ksplit range of 384.
// ---------------------------------------------------------------------------
__global__ __launch_bounds__(256)
void kgates(const float* __restrict__ x, const float* __restrict__ h0,
            const float* __restrict__ x2f, const float* __restrict__ x2i,
            const float* __restrict__ x2o, const float* __restrict__ x2c,
            const float* __restrict__ h2f, const float* __restrict__ h2i,
            const float* __restrict__ h2o, const float* __restrict__ w)
{
    __shared__ __align__(16) float sA[64][36];
    __shared__ __align__(16) float sB[64][36];

    int tid = threadIdx.x;
    int gate = blockIdx.z;
    int bn0 = blockIdx.x * 64;             // output k offset
    int bm0 = (blockIdx.y & 3) * 64;       // batch row offset
    int ks  = blockIdx.y >> 2;             // K split 0/1
    int kbeg = ks * 384;

    const float* xw = (gate == 0) ? x2f : (gate == 1) ? x2i
                    : (gate == 2) ? x2o : x2c;
    const float* hw = (gate == 0) ? h2f : (gate == 1) ? h2i
                    : (gate == 2) ? h2o : w;

    int wid = tid >> 5;                    // 8 warps
    int wr = wid & 3;                      // row frag (16 rows)
    int wc = wid >> 2;                     // 0..1 col half (32 cols)

    wmma::fragment<wmma::accumulator, 16, 16, 8, float> acc[2];
    wmma::fill_fragment(acc[0], 0.0f);
    wmma::fill_fragment(acc[1], 0.0f);

    wmma::fragment<wmma::matrix_a, 16, 16, 8, wmma::precision::tf32,
                   wmma::row_major> araw, ahi, alo;
    wmma::fragment<wmma::matrix_b, 16, 16, 8, wmma::precision::tf32,
                   wmma::col_major> braw, bhi, blo;

    for (int k0 = kbeg; k0 < kbeg + 384; k0 += 32) {
        // ---- stage A (64 x 32 raw fp32) -----------------------------------
#pragma unroll
        for (int l = 0; l < 2; l++) {
            int e4 = tid + l * 256;
            int row = e4 >> 3;
            int c4 = (e4 & 7) * 4;
            int col = k0 + c4;
            const float* src = (col < 256)
                ? (x  + (size_t)(bm0 + row) * ISIZE + col)
                : (h0 + (size_t)(bm0 + row) * HSIZE + col - 256);
            *(float4*)&sA[row][c4] = *(const float4*)src;
        }
        // ---- stage B (64 x 32 raw fp32) -----------------------------------
        bool trans = (gate == 3) && (k0 >= 256);   // w is [h,k]
        if (!trans) {
#pragma unroll
            for (int l = 0; l < 2; l++) {
                int e4 = tid + l * 256;
                int row = e4 >> 3;
                int c4 = (e4 & 7) * 4;
                int col = k0 + c4;
                const float* src = (col < 256)
                    ? (xw + (size_t)(bn0 + row) * ISIZE + col)
                    : (hw + (size_t)(bn0 + row) * HSIZE + col - 256);
                *(float4*)&sB[row][c4] = *(const float4*)src;
            }
        } else {
#pragma unroll
            for (int l = 0; l < 8; l++) {
                int e = tid + l * 256;
                int n = e & 63;
                int kk = e >> 6;
                sB[n][kk] = w[(size_t)(k0 + kk - 256) * HSIZE + bn0 + n];
            }
        }
        __syncthreads();

        // ---- tensor math: 4 k-subs of 8, hi/lo split in regs --------------
#pragma unroll
        for (int s8 = 0; s8 < 4; s8++) {
            wmma::load_matrix_sync(araw, &sA[wr * 16][s8 * 8], 36);
#pragma unroll
            for (int i = 0; i < araw.num_elements; i++)
                cvt2(araw.x[i], ahi.x[i], alo.x[i]);
#pragma unroll
            for (int j = 0; j < 2; j++) {
                int n0 = (wc * 2 + j) * 16;
                wmma::load_matrix_sync(braw, &sB[n0][s8 * 8], 36);
#pragma unroll
                for (int i = 0; i < braw.num_elements; i++)
                    cvt2(braw.x[i], bhi.x[i], blo.x[i]);
                wmma::mma_sync(acc[j], ahi, bhi, acc[j]);
                wmma::mma_sync(acc[j], ahi, blo, acc[j]);
                wmma::mma_sync(acc[j], alo, bhi, acc[j]);
            }
        }
        __syncthreads();
    }

    float* outb = (ks == 0 ? g_preA : g_preB) + (size_t)gate * BH;
#pragma unroll
    for (int j = 0; j < 2; j++)
        wmma::store_matrix_sync(outb + (size_t)(bm0 + wr * 16) * HSIZE
                                     + bn0 + (wc * 2 + j) * 16,
                                acc[j], HSIZE, wmma::mem_row_major);
}

// ---------------------------------------------------------------------------
// KREDUCE v3: K3-shaped streaming. 2048 blocks x 256 thr, barrier-free.
// Block u = (b, 64-row chunk). Thread: group g (32 rows), f4 col c.
// ---------------------------------------------------------------------------
__global__ __launch_bounds__(256)
void kreduce(const float* __restrict__ h0, const float* __restrict__ hebb)
{
    int u = blockIdx.x;
    int b = u >> 3;
    int ch = u & 7;
    int g = threadIdx.x >> 7;          // 0..1
    int c = threadIdx.x & 127;         // f4 column
    int r0 = ch * 64 + g * 32;
    const float4* hb4 = (const float4*)(hebb + (size_t)b * HSIZE * HSIZE)
                        + (size_t)r0 * 128 + c;
    const float* h0p = h0 + b * HSIZE + r0;
    float4 acc = make_float4(0.f, 0.f, 0.f, 0.f);
#pragma unroll 8
    for (int i = 0; i < 32; ++i) {
        float sv = __ldg(h0p + i);
        float4 v = hb4[(size_t)i * 128];
        acc.x = fmaf(sv, v.x, acc.x);
        acc.y = fmaf(sv, v.y, acc.y);
        acc.z = fmaf(sv, v.z, acc.z);
        acc.w = fmaf(sv, v.w, acc.w);
    }
    int p = ch * 2 + g;                // 0..15
    ((float4*)(g_hredp + (size_t)p * BH + b * HSIZE))[c] = acc;
}

// ---------------------------------------------------------------------------
// K2: per-batch cell/hactiv + modulation scalar + ei = (m*mfw+mfb)*its.
// ---------------------------------------------------------------------------
__global__ __launch_bounds__(HSIZE)
void k2(const float* __restrict__ c0, const float* __restrict__ alpha,
        const float* __restrict__ x2f_b, const float* __restrict__ h2f_b,
        const float* __restrict__ x2i_b, const float* __restrict__ h2i_b,
        const float* __restrict__ x2o_b, const float* __restrict__ h2o_b,
        const float* __restrict__ x2c_b,
        const float* __restrict__ h2mod_w, const float* __restrict__ h2mod_b,
        const float* __restrict__ mfw, const float* __restrict__ mfb,
        float* __restrict__ out_hact, float* __restrict__ out_cell)
{
    __shared__ float sred[16];
    __shared__ float smv;
    int b = blockIdx.x;
    int k = threadIdx.x;
    int idx = b * HSIZE + k;

    float hred = 0.f;
#pragma unroll
    for (int p = 0; p < 16; p++) hred += g_hredp[(size_t)p * BH + idx];

    float pf = g_preA[idx]          + g_preB[idx]          + x2f_b[k] + h2f_b[k];
    float pi = g_preA[BH + idx]     + g_preB[BH + idx]     + x2i_b[k] + h2i_b[k];
    float po = g_preA[2 * BH + idx] + g_preB[2 * BH + idx] + x2o_b[k] + h2o_b[k];
    float pc = g_preA[3 * BH + idx] + g_preB[3 * BH + idx] + x2c_b[k]
             + alpha[k] * hred;
    float fgt = 1.f / (1.f + expf(-pf));
    float ipt = 1.f / (1.f + expf(-pi));
    float opt = 1.f / (1.f + expf(-po));
    float its = tanhf(pc);
    float cell = fgt * c0[idx] + ipt * its;
    float hact = opt * tanhf(cell);
    out_cell[idx] = cell;
    out_hact[idx] = hact;

    float mv = hact * h2mod_w[k];
#pragma unroll
    for (int o = 16; o > 0; o >>= 1) mv += __shfl_down_sync(0xffffffffu, mv, o);
    if ((k & 31) == 0) sred[k >> 5] = mv;
    __syncthreads();
    if (k == 0) {
        float s = 0.f;
#pragma unroll
        for (int i = 0; i < 16; i++) s += sred[i];
        smv = tanhf(s + h2mod_b[0]);
    }
    __syncthreads();
    g_ei[idx] = fmaf(smv, mfw[k], mfb[k]) * its;
}

// ---------------------------------------------------------------------------
// K3: hebb_new[b,h,k] = clip(hebb + h0[b,h]*ei[b,k], -2, 2). Pure streaming.
// ---------------------------------------------------------------------------
__global__ __launch_bounds__(256)
void k3(const float4* __restrict__ hebb4, const float* __restrict__ h0,
        float4* __restrict__ out4)
{
    const float4* ei4 = reinterpret_cast<const float4*>(g_ei);
    int base = blockIdx.x * 1024 + threadIdx.x;
#pragma unroll
    for (int j = 0; j < 4; j++) {
        int idx = base + j * 256;
        int k4 = idx & 127;
        int bh = idx >> 7;
        int b = bh >> 9;
        float s = h0[bh];
        float4 e = ei4[(b << 7) + k4];
        float4 hv = hebb4[idx];
        float v;
        v = fmaf(s, e.x, hv.x); hv.x = fminf(fmaxf(v, -2.f), 2.f);
        v = fmaf(s, e.y, hv.y); hv.y = fminf(fmaxf(v, -2.f), 2.f);
        v = fmaf(s, e.z, hv.z); hv.z = fminf(fmaxf(v, -2.f), 2.f);
        v = fmaf(s, e.w, hv.w); hv.w = fminf(fmaxf(v, -2.f), 2.f);
        out4[idx] = hv;
    }
}

// ---------------------------------------------------------------------------
extern "C" void kernel_launch(void* const* d_in, const int* in_sizes, int n_in,
                              void* d_out, int out_size)
{
    const float* inputs  = (const float*)d_in[0];
    const float* h0      = (const float*)d_in[1];
    const float* c0      = (const float*)d_in[2];
    const float* hebb    = (const float*)d_in[3];
    const float* w       = (const float*)d_in[4];
    const float* alpha   = (const float*)d_in[5];
    const float* h2f_w   = (const float*)d_in[6];
    const float* h2f_b   = (const float*)d_in[7];
    const float* h2i_w   = (const float*)d_in[8];
    const float* h2i_b   = (const float*)d_in[9];
    const float* h2o_w   = (const float*)d_in[10];
    const float* h2o_b   = (const float*)d_in[11];
    const float* x2f_w   = (const float*)d_in[12];
    const float* x2f_b   = (const float*)d_in[13];
    const float* x2i_w   = (const float*)d_in[14];
    const float* x2i_b   = (const float*)d_in[15];
    const float* x2o_w   = (const float*)d_in[16];
    const float* x2o_b   = (const float*)d_in[17];
    const float* x2c_w   = (const float*)d_in[18];
    const float* x2c_b   = (const float*)d_in[19];
    const float* h2mod_w = (const float*)d_in[20];
    const float* h2mod_b = (const float*)d_in[21];
    const float* mfw     = (const float*)d_in[22];
    const float* mfb     = (const float*)d_in[23];

    float* out       = (float*)d_out;
    float* out_hact  = out;              // [B,H]
    float* out_cell  = out + BH;         // [B,H]
    float* out_hebb  = out + 2 * BH;     // [B,H,H]

    // 1) tensor-core gate GEMM, K-split x2 -> 256 blocks
    dim3 gg(8, 8, 4);
    kgates<<<gg, 256>>>(inputs, h0, x2f_w, x2i_w, x2o_w, x2c_w,
                        h2f_w, h2i_w, h2o_w, w);

    // 2) streaming hebb reduction (268MB read, K3-shaped)
    kreduce<<<2048, 256>>>(h0, hebb);

    // 3) cell / hactiv / m / ei
    k2<<<BSZ, HSIZE>>>(c0, alpha, x2f_b, h2f_b, x2i_b, h2i_b, x2o_b, h2o_b,
                       x2c_b, h2mod_w, h2mod_b, mfw, mfb, out_hact, out_cell);

    // 4) hebb update (268MB R + 268MB W streaming)
    int nblk = (BSZ * HSIZE * HSIZE / 4) / 1024;   // 16384
    k3<<<nblk, 256>>>((const float4*)hebb, h0, (float4*)out_hebb);
}

// round 16
// speedup vs baseline: 1.6541x; 1.1923x over previous
#include <cuda_runtime.h>
#include <mma.h>
#include <math.h>

using namespace nvcuda;

#define BSZ   256
#define ISIZE 256
#define HSIZE 512
#define BH    (BSZ*HSIZE)

#define NGB   256              // gate blocks (4 gates x 8 col x 4 row x 2 ksplit)
#define NRB   2048             // reduce blocks (b, 64-row chunk)

// Scratch (device globals)
__device__ __align__(16) float g_preA[4*BH];    // gate partials, K 0..383
__device__ __align__(16) float g_preB[4*BH];    // gate partials, K 384..767
__device__ __align__(16) float g_hredp[16*BH];  // hred partials (16 slots)
__device__ __align__(16) float g_ei[BH];        // eta*its per (b,k)

// split v into hi (tf32-truncated) + lo (exact residue)
__device__ __forceinline__ void cvt2(float v, float& hi, float& lo)
{
    hi = __uint_as_float(__float_as_uint(v) & 0xffffe000u);
    lo = v - hi;
}

// ---------------------------------------------------------------------------
// K1: ONE launch, 2304 blocks x 256 thr.
//  bid [0,256):    tf32 tensor gate blocks (64x64 tile, K=384 chunk) --
//                  tensor+L2 work, hidden under the reduce's DRAM stream.
//  bid [256,2304): reduce blocks (b, 64-row chunk), barrier-free streaming.
// ---------------------------------------------------------------------------
__global__ __launch_bounds__(256)
void k1(const float* __restrict__ x, const float* __restrict__ h0,
        const float* __restrict__ hebb,
        const float* __restrict__ x2f, const float* __restrict__ x2i,
        const float* __restrict__ x2o, const float* __restrict__ x2c,
        const float* __restrict__ h2f, const float* __restrict__ h2i,
        const float* __restrict__ h2o, const float* __restrict__ w)
{
    __shared__ __align__(16) float sA[64][36];
    __shared__ __align__(16) float sB[64][36];

    int tid = threadIdx.x;
    int bid = blockIdx.x;

    if (bid >= NGB) {
        // ---------------- reduce block: (b, 64-row chunk) ------------------
        int u = bid - NGB;
        int b = u >> 3;
        int ch = u & 7;
        int g = tid >> 7;              // 0..1 (32 rows each)
        int c = tid & 127;             // f4 column
        int r0 = ch * 64 + g * 32;
        const float4* hb4 = (const float4*)(hebb + (size_t)b * HSIZE * HSIZE)
                            + (size_t)r0 * 128 + c;
        const float* h0p = h0 + b * HSIZE + r0;
        float4 acc = make_float4(0.f, 0.f, 0.f, 0.f);
#pragma unroll 8
        for (int i = 0; i < 32; ++i) {
            float sv = __ldg(h0p + i);
            float4 v = hb4[(size_t)i * 128];
            acc.x = fmaf(sv, v.x, acc.x);
            acc.y = fmaf(sv, v.y, acc.y);
            acc.z = fmaf(sv, v.z, acc.z);
            acc.w = fmaf(sv, v.w, acc.w);
        }
        int p = ch * 2 + g;            // 0..15
        ((float4*)(g_hredp + (size_t)p * BH + b * HSIZE))[c] = acc;
        return;
    }

    // ---------------- gate block: tf32 tensor GEMM -------------------------
    int gate = bid >> 6;
    int gb = bid & 63;
    int bn0 = (gb & 7) * 64;               // output k offset
    int bm0 = ((gb >> 3) & 3) * 64;        // batch row offset
    int ks  = gb >> 5;                     // K split 0/1
    int kbeg = ks * 384;

    const float* xw = (gate == 0) ? x2f : (gate == 1) ? x2i
                    : (gate == 2) ? x2o : x2c;
    const float* hw = (gate == 0) ? h2f : (gate == 1) ? h2i
                    : (gate == 2) ? h2o : w;

    int wid = tid >> 5;                    // 8 warps
    int wr = wid & 3;                      // row frag (16 rows)
    int wc = wid >> 2;                     // 0..1 col half (32 cols)

    wmma::fragment<wmma::accumulator, 16, 16, 8, float> acc[2];
    wmma::fill_fragment(acc[0], 0.0f);
    wmma::fill_fragment(acc[1], 0.0f);

    wmma::fragment<wmma::matrix_a, 16, 16, 8, wmma::precision::tf32,
                   wmma::row_major> araw, ahi, alo;
    wmma::fragment<wmma::matrix_b, 16, 16, 8, wmma::precision::tf32,
                   wmma::col_major> braw, bhi, blo;

    for (int k0 = kbeg; k0 < kbeg + 384; k0 += 32) {
        // ---- stage A (64 x 32 raw fp32) -----------------------------------
#pragma unroll
        for (int l = 0; l < 2; l++) {
            int e4 = tid + l * 256;
            int row = e4 >> 3;
            int c4 = (e4 & 7) * 4;
            int col = k0 + c4;
            const float* src = (col < 256)
                ? (x  + (size_t)(bm0 + row) * ISIZE + col)
                : (h0 + (size_t)(bm0 + row) * HSIZE + col - 256);
            *(float4*)&sA[row][c4] = *(const float4*)src;
        }
        // ---- stage B (64 x 32 raw fp32) -----------------------------------
        bool trans = (gate == 3) && (k0 >= 256);   // w is [h,k]
        if (!trans) {
#pragma unroll
            for (int l = 0; l < 2; l++) {
                int e4 = tid + l * 256;
                int row = e4 >> 3;
                int c4 = (e4 & 7) * 4;
                int col = k0 + c4;
                const float* src = (col < 256)
                    ? (xw + (size_t)(bn0 + row) * ISIZE + col)
                    : (hw + (size_t)(bn0 + row) * HSIZE + col - 256);
                *(float4*)&sB[row][c4] = *(const float4*)src;
            }
        } else {
#pragma unroll
            for (int l = 0; l < 8; l++) {
                int e = tid + l * 256;
                int n = e & 63;
                int kk = e >> 6;
                sB[n][kk] = w[(size_t)(k0 + kk - 256) * HSIZE + bn0 + n];
            }
        }
        __syncthreads();

        // ---- tensor math: 4 k-subs of 8, hi/lo split in regs --------------
#pragma unroll
        for (int s8 = 0; s8 < 4; s8++) {
            wmma::load_matrix_sync(araw, &sA[wr * 16][s8 * 8], 36);
#pragma unroll
            for (int i = 0; i < araw.num_elements; i++)
                cvt2(araw.x[i], ahi.x[i], alo.x[i]);
#pragma unroll
            for (int j = 0; j < 2; j++) {
                int n0 = (wc * 2 + j) * 16;
                wmma::load_matrix_sync(braw, &sB[n0][s8 * 8], 36);
#pragma unroll
                for (int i = 0; i < braw.num_elements; i++)
                    cvt2(braw.x[i], bhi.x[i], blo.x[i]);
                wmma::mma_sync(acc[j], ahi, bhi, acc[j]);
                wmma::mma_sync(acc[j], ahi, blo, acc[j]);
                wmma::mma_sync(acc[j], alo, bhi, acc[j]);
            }
        }
        __syncthreads();
    }

    float* outb = (ks == 0 ? g_preA : g_preB) + (size_t)gate * BH;
#pragma unroll
    for (int j = 0; j < 2; j++)
        wmma::store_matrix_sync(outb + (size_t)(bm0 + wr * 16) * HSIZE
                                     + bn0 + (wc * 2 + j) * 16,
                                acc[j], HSIZE, wmma::mem_row_major);
}

// ---------------------------------------------------------------------------
// K2: per-batch cell/hactiv + modulation scalar + ei = (m*mfw+mfb)*its.
// ---------------------------------------------------------------------------
__global__ __launch_bounds__(HSIZE)
void k2(const float* __restrict__ c0, const float* __restrict__ alpha,
        const float* __restrict__ x2f_b, const float* __restrict__ h2f_b,
        const float* __restrict__ x2i_b, const float* __restrict__ h2i_b,
        const float* __restrict__ x2o_b, const float* __restrict__ h2o_b,
        const float* __restrict__ x2c_b,
        const float* __restrict__ h2mod_w, const float* __restrict__ h2mod_b,
        const float* __restrict__ mfw, const float* __restrict__ mfb,
        float* __restrict__ out_hact, float* __restrict__ out_cell)
{
    __shared__ float sred[16];
    __shared__ float smv;
    int b = blockIdx.x;
    int k = threadIdx.x;
    int idx = b * HSIZE + k;

    float hred = 0.f;
#pragma unroll
    for (int p = 0; p < 16; p++) hred += g_hredp[(size_t)p * BH + idx];

    float pf = g_preA[idx]          + g_preB[idx]          + x2f_b[k] + h2f_b[k];
    float pi = g_preA[BH + idx]     + g_preB[BH + idx]     + x2i_b[k] + h2i_b[k];
    float po = g_preA[2 * BH + idx] + g_preB[2 * BH + idx] + x2o_b[k] + h2o_b[k];
    float pc = g_preA[3 * BH + idx] + g_preB[3 * BH + idx] + x2c_b[k]
             + alpha[k] * hred;
    float fgt = 1.f / (1.f + expf(-pf));
    float ipt = 1.f / (1.f + expf(-pi));
    float opt = 1.f / (1.f + expf(-po));
    float its = tanhf(pc);
    float cell = fgt * c0[idx] + ipt * its;
    float hact = opt * tanhf(cell);
    out_cell[idx] = cell;
    out_hact[idx] = hact;

    float mv = hact * h2mod_w[k];
#pragma unroll
    for (int o = 16; o > 0; o >>= 1) mv += __shfl_down_sync(0xffffffffu, mv, o);
    if ((k & 31) == 0) sred[k >> 5] = mv;
    __syncthreads();
    if (k == 0) {
        float s = 0.f;
#pragma unroll
        for (int i = 0; i < 16; i++) s += sred[i];
        smv = tanhf(s + h2mod_b[0]);
    }
    __syncthreads();
    g_ei[idx] = fmaf(smv, mfw[k], mfb[k]) * its;
}

// ---------------------------------------------------------------------------
// K3: hebb_new[b,h,k] = clip(hebb + h0[b,h]*ei[b,k], -2, 2). Pure streaming.
// ---------------------------------------------------------------------------
__global__ __launch_bounds__(256)
void k3(const float4* __restrict__ hebb4, const float* __restrict__ h0,
        float4* __restrict__ out4)
{
    const float4* ei4 = reinterpret_cast<const float4*>(g_ei);
    int base = blockIdx.x * 1024 + threadIdx.x;
#pragma unroll
    for (int j = 0; j < 4; j++) {
        int idx = base + j * 256;
        int k4 = idx & 127;
        int bh = idx >> 7;
        int b = bh >> 9;
        float s = h0[bh];
        float4 e = ei4[(b << 7) + k4];
        float4 hv = hebb4[idx];
        float v;
        v = fmaf(s, e.x, hv.x); hv.x = fminf(fmaxf(v, -2.f), 2.f);
        v = fmaf(s, e.y, hv.y); hv.y = fminf(fmaxf(v, -2.f), 2.f);
        v = fmaf(s, e.z, hv.z); hv.z = fminf(fmaxf(v, -2.f), 2.f);
        v = fmaf(s, e.w, hv.w); hv.w = fminf(fmaxf(v, -2.f), 2.f);
        out4[idx] = hv;
    }
}

// ---------------------------------------------------------------------------
extern "C" void kernel_launch(void* const* d_in, const int* in_sizes, int n_in,
                              void* d_out, int out_size)
{
    const float* inputs  = (const float*)d_in[0];
    const float* h0      = (const float*)d_in[1];
    const float* c0      = (const float*)d_in[2];
    const float* hebb    = (const float*)d_in[3];
    const float* w       = (const float*)d_in[4];
    const float* alpha   = (const float*)d_in[5];
    const float* h2f_w   = (const float*)d_in[6];
    const float* h2f_b   = (const float*)d_in[7];
    const float* h2i_w   = (const float*)d_in[8];
    const float* h2i_b   = (const float*)d_in[9];
    const float* h2o_w   = (const float*)d_in[10];
    const float* h2o_b   = (const float*)d_in[11];
    const float* x2f_w   = (const float*)d_in[12];
    const float* x2f_b   = (const float*)d_in[13];
    const float* x2i_w   = (const float*)d_in[14];
    const float* x2i_b   = (const float*)d_in[15];
    const float* x2o_w   = (const float*)d_in[16];
    const float* x2o_b   = (const float*)d_in[17];
    const float* x2c_w   = (const float*)d_in[18];
    const float* x2c_b   = (const float*)d_in[19];
    const float* h2mod_w = (const float*)d_in[20];
    const float* h2mod_b = (const float*)d_in[21];
    const float* mfw     = (const float*)d_in[22];
    const float* mfb     = (const float*)d_in[23];

    float* out       = (float*)d_out;
    float* out_hact  = out;              // [B,H]
    float* out_cell  = out + BH;         // [B,H]
    float* out_hebb  = out + 2 * BH;     // [B,H,H]

    // 1) gates (tensor pipe) + hebb reduction (DRAM stream) in ONE launch
    k1<<<NGB + NRB, 256>>>(inputs, h0, hebb,
                           x2f_w, x2i_w, x2o_w, x2c_w,
                           h2f_w, h2i_w, h2o_w, w);

    // 2) cell / hactiv / m / ei
    k2<<<BSZ, HSIZE>>>(c0, alpha, x2f_b, h2f_b, x2i_b, h2i_b, x2o_b, h2o_b,
                       x2c_b, h2mod_w, h2mod_b, mfw, mfb, out_hact, out_cell);

    // 3) hebb update (268MB R + 268MB W streaming)
    int nblk = (BSZ * HSIZE * HSIZE / 4) / 1024;   // 16384
    k3<<<nblk, 256>>>((const float4*)hebb, h0, (float4*)out_hebb);
}

// round 17
// speedup vs baseline: 1.6823x; 1.0171x over previous
#include <cuda_runtime.h>
#include <cuda_bf16.h>
#include <mma.h>
#include <math.h>

using namespace nvcuda;

#define BSZ   256
#define ISIZE 256
#define HSIZE 512
#define BH    (BSZ*HSIZE)

#define NGB   256              // gate blocks (4 gates x 8 col x 4 row x 2 ksplit)
#define NRB   2048             // reduce blocks (b, 64-row chunk)

// Scratch (device globals)
__device__ __align__(16) float g_preA[4*BH];    // gate partials, K 0..383
__device__ __align__(16) float g_preB[4*BH];    // gate partials, K 384..767
__device__ __align__(16) float g_hredp[16*BH];  // hred partials (16 slots)
__device__ __align__(16) float g_ei[BH];        // eta*its per (b,k)

// split v into bf16 hi + bf16 lo (v ~ hi + lo, err ~2^-17 |v|)
__device__ __forceinline__ void bsplit(float v, __nv_bfloat16& hi, __nv_bfloat16& lo)
{
    hi = __float2bfloat16(v);
    lo = __float2bfloat16(v - __bfloat162float(hi));
}

// ---------------------------------------------------------------------------
// K1: ONE launch, 2304 blocks x 256 thr.
//  bid [0,256):    bf16 tensor gate blocks (64x64 tile, K=384 chunk),
//                  hi/lo error-compensated (3 mma per k16-step).
//  bid [256,2304): reduce blocks (b, 64-row chunk), barrier-free streaming.
// ---------------------------------------------------------------------------
__global__ __launch_bounds__(256)
void k1(const float* __restrict__ x, const float* __restrict__ h0,
        const float* __restrict__ hebb,
        const float* __restrict__ x2f, const float* __restrict__ x2i,
        const float* __restrict__ x2o, const float* __restrict__ x2c,
        const float* __restrict__ h2f, const float* __restrict__ h2i,
        const float* __restrict__ h2o, const float* __restrict__ w)
{
    __shared__ __align__(16) __nv_bfloat16 sAhi[64][40], sAlo[64][40];
    __shared__ __align__(16) __nv_bfloat16 sBhi[64][40], sBlo[64][40];

    int tid = threadIdx.x;
    int bid = blockIdx.x;

    if (bid >= NGB) {
        // ---------------- reduce block: (b, 64-row chunk) ------------------
        int u = bid - NGB;
        int b = u >> 3;
        int ch = u & 7;
        int g = tid >> 7;              // 0..1 (32 rows each)
        int c = tid & 127;             // f4 column
        int r0 = ch * 64 + g * 32;
        const float4* hb4 = (const float4*)(hebb + (size_t)b * HSIZE * HSIZE)
                            + (size_t)r0 * 128 + c;
        const float* h0p = h0 + b * HSIZE + r0;
        float4 acc = make_float4(0.f, 0.f, 0.f, 0.f);
#pragma unroll 8
        for (int i = 0; i < 32; ++i) {
            float sv = __ldg(h0p + i);
            float4 v = hb4[(size_t)i * 128];
            acc.x = fmaf(sv, v.x, acc.x);
            acc.y = fmaf(sv, v.y, acc.y);
            acc.z = fmaf(sv, v.z, acc.z);
            acc.w = fmaf(sv, v.w, acc.w);
        }
        int p = ch * 2 + g;            // 0..15
        ((float4*)(g_hredp + (size_t)p * BH + b * HSIZE))[c] = acc;
        return;
    }

    // ---------------- gate block: bf16 tensor GEMM, hi/lo compensated ------
    int gate = bid >> 6;
    int gb = bid & 63;
    int bn0 = (gb & 7) * 64;               // output k offset
    int bm0 = ((gb >> 3) & 3) * 64;        // batch row offset
    int ks  = gb >> 5;                     // K split 0/1
    int kbeg = ks * 384;

    const float* xw = (gate == 0) ? x2f : (gate == 1) ? x2i
                    : (gate == 2) ? x2o : x2c;
    const float* hw = (gate == 0) ? h2f : (gate == 1) ? h2i
                    : (gate == 2) ? h2o : w;

    int wid = tid >> 5;                    // 8 warps
    int wr = wid & 3;                      // row frag (16 rows)
    int wc = wid >> 2;                     // 0..1 col half (32 cols)

    wmma::fragment<wmma::accumulator, 16, 16, 16, float> acc[2];
    wmma::fill_fragment(acc[0], 0.0f);
    wmma::fill_fragment(acc[1], 0.0f);

    wmma::fragment<wmma::matrix_a, 16, 16, 16, __nv_bfloat16,
                   wmma::row_major> ahi, alo;
    wmma::fragment<wmma::matrix_b, 16, 16, 16, __nv_bfloat16,
                   wmma::col_major> bhi, blo;

    for (int k0 = kbeg; k0 < kbeg + 384; k0 += 32) {
        // ---- stage A (64 x 32), hi/lo split at staging --------------------
#pragma unroll
        for (int l = 0; l < 2; l++) {
            int e4 = tid + l * 256;
            int row = e4 >> 3;
            int c4 = (e4 & 7) * 4;
            int col = k0 + c4;
            const float* src = (col < 256)
                ? (x  + (size_t)(bm0 + row) * ISIZE + col)
                : (h0 + (size_t)(bm0 + row) * HSIZE + col - 256);
            float4 v = *(const float4*)src;
            bsplit(v.x, sAhi[row][c4    ], sAlo[row][c4    ]);
            bsplit(v.y, sAhi[row][c4 + 1], sAlo[row][c4 + 1]);
            bsplit(v.z, sAhi[row][c4 + 2], sAlo[row][c4 + 2]);
            bsplit(v.w, sAhi[row][c4 + 3], sAlo[row][c4 + 3]);
        }
        // ---- stage B (64 x 32), hi/lo split at staging --------------------
        bool trans = (gate == 3) && (k0 >= 256);   // w is [h,k]
        if (!trans) {
#pragma unroll
            for (int l = 0; l < 2; l++) {
                int e4 = tid + l * 256;
                int row = e4 >> 3;
                int c4 = (e4 & 7) * 4;
                int col = k0 + c4;
                const float* src = (col < 256)
                    ? (xw + (size_t)(bn0 + row) * ISIZE + col)
                    : (hw + (size_t)(bn0 + row) * HSIZE + col - 256);
                float4 v = *(const float4*)src;
                bsplit(v.x, sBhi[row][c4    ], sBlo[row][c4    ]);
                bsplit(v.y, sBhi[row][c4 + 1], sBlo[row][c4 + 1]);
                bsplit(v.z, sBhi[row][c4 + 2], sBlo[row][c4 + 2]);
                bsplit(v.w, sBhi[row][c4 + 3], sBlo[row][c4 + 3]);
            }
        } else {
#pragma unroll
            for (int l = 0; l < 8; l++) {
                int e = tid + l * 256;
                int n = e & 63;
                int kk = e >> 6;
                float v = w[(size_t)(k0 + kk - 256) * HSIZE + bn0 + n];
                bsplit(v, sBhi[n][kk], sBlo[n][kk]);
            }
        }
        __syncthreads();

        // ---- tensor math: 2 k16-subs, 3 mma each --------------------------
#pragma unroll
        for (int s16 = 0; s16 < 2; s16++) {
            wmma::load_matrix_sync(ahi, &sAhi[wr * 16][s16 * 16], 40);
            wmma::load_matrix_sync(alo, &sAlo[wr * 16][s16 * 16], 40);
#pragma unroll
            for (int j = 0; j < 2; j++) {
                int n0 = (wc * 2 + j) * 16;
                wmma::load_matrix_sync(bhi, &sBhi[n0][s16 * 16], 40);
                wmma::load_matrix_sync(blo, &sBlo[n0][s16 * 16], 40);
                wmma::mma_sync(acc[j], ahi, bhi, acc[j]);
                wmma::mma_sync(acc[j], ahi, blo, acc[j]);
                wmma::mma_sync(acc[j], alo, bhi, acc[j]);
            }
        }
        __syncthreads();
    }

    float* outb = (ks == 0 ? g_preA : g_preB) + (size_t)gate * BH;
#pragma unroll
    for (int j = 0; j < 2; j++)
        wmma::store_matrix_sync(outb + (size_t)(bm0 + wr * 16) * HSIZE
                                     + bn0 + (wc * 2 + j) * 16,
                                acc[j], HSIZE, wmma::mem_row_major);
}

// ---------------------------------------------------------------------------
// K2: per-batch cell/hactiv + modulation scalar + ei = (m*mfw+mfb)*its.
// ---------------------------------------------------------------------------
__global__ __launch_bounds__(HSIZE)
void k2(const float* __restrict__ c0, const float* __restrict__ alpha,
        const float* __restrict__ x2f_b, const float* __restrict__ h2f_b,
        const float* __restrict__ x2i_b, const float* __restrict__ h2i_b,
        const float* __restrict__ x2o_b, const float* __restrict__ h2o_b,
        const float* __restrict__ x2c_b,
        const float* __restrict__ h2mod_w, const float* __restrict__ h2mod_b,
        const float* __restrict__ mfw, const float* __restrict__ mfb,
        float* __restrict__ out_hact, float* __restrict__ out_cell)
{
    __shared__ float sred[16];
    __shared__ float smv;
    int b = blockIdx.x;
    int k = threadIdx.x;
    int idx = b * HSIZE + k;

    float hred = 0.f;
#pragma unroll
    for (int p = 0; p < 16; p++) hred += g_hredp[(size_t)p * BH + idx];

    float pf = g_preA[idx]          + g_preB[idx]          + x2f_b[k] + h2f_b[k];
    float pi = g_preA[BH + idx]     + g_preB[BH + idx]     + x2i_b[k] + h2i_b[k];
    float po = g_preA[2 * BH + idx] + g_preB[2 * BH + idx] + x2o_b[k] + h2o_b[k];
    float pc = g_preA[3 * BH + idx] + g_preB[3 * BH + idx] + x2c_b[k]
             + alpha[k] * hred;
    float fgt = 1.f / (1.f + expf(-pf));
    float ipt = 1.f / (1.f + expf(-pi));
    float opt = 1.f / (1.f + expf(-po));
    float its = tanhf(pc);
    float cell = fgt * c0[idx] + ipt * its;
    float hact = opt * tanhf(cell);
    out_cell[idx] = cell;
    out_hact[idx] = hact;

    float mv = hact * h2mod_w[k];
#pragma unroll
    for (int o = 16; o > 0; o >>= 1) mv += __shfl_down_sync(0xffffffffu, mv, o);
    if ((k & 31) == 0) sred[k >> 5] = mv;
    __syncthreads();
    if (k == 0) {
        float s = 0.f;
#pragma unroll
        for (int i = 0; i < 16; i++) s += sred[i];
        smv = tanhf(s + h2mod_b[0]);
    }
    __syncthreads();
    g_ei[idx] = fmaf(smv, mfw[k], mfb[k]) * its;
}

// ---------------------------------------------------------------------------
// K3: hebb_new[b,h,k] = clip(hebb + h0[b,h]*ei[b,k], -2, 2). Pure streaming.
// ---------------------------------------------------------------------------
__global__ __launch_bounds__(256)
void k3(const float4* __restrict__ hebb4, const float* __restrict__ h0,
        float4* __restrict__ out4)
{
    const float4* ei4 = reinterpret_cast<const float4*>(g_ei);
    int base = blockIdx.x * 1024 + threadIdx.x;
#pragma unroll
    for (int j = 0; j < 4; j++) {
        int idx = base + j * 256;
        int k4 = idx & 127;
        int bh = idx >> 7;
        int b = bh >> 9;
        float s = h0[bh];
        float4 e = ei4[(b << 7) + k4];
        float4 hv = hebb4[idx];
        float v;
        v = fmaf(s, e.x, hv.x); hv.x = fminf(fmaxf(v, -2.f), 2.f);
        v = fmaf(s, e.y, hv.y); hv.y = fminf(fmaxf(v, -2.f), 2.f);
        v = fmaf(s, e.z, hv.z); hv.z = fminf(fmaxf(v, -2.f), 2.f);
        v = fmaf(s, e.w, hv.w); hv.w = fminf(fmaxf(v, -2.f), 2.f);
        out4[idx] = hv;
    }
}

// ---------------------------------------------------------------------------
extern "C" void kernel_launch(void* const* d_in, const int* in_sizes, int n_in,
                              void* d_out, int out_size)
{
    const float* inputs  = (const float*)d_in[0];
    const float* h0      = (const float*)d_in[1];
    const float* c0      = (const float*)d_in[2];
    const float* hebb    = (const float*)d_in[3];
    const float* w       = (const float*)d_in[4];
    const float* alpha   = (const float*)d_in[5];
    const float* h2f_w   = (const float*)d_in[6];
    const float* h2f_b   = (const float*)d_in[7];
    const float* h2i_w   = (const float*)d_in[8];
    const float* h2i_b   = (const float*)d_in[9];
    const float* h2o_w   = (const float*)d_in[10];
    const float* h2o_b   = (const float*)d_in[11];
    const float* x2f_w   = (const float*)d_in[12];
    const float* x2f_b   = (const float*)d_in[13];
    const float* x2i_w   = (const float*)d_in[14];
    const float* x2i_b   = (const float*)d_in[15];
    const float* x2o_w   = (const float*)d_in[16];
    const float* x2o_b   = (const float*)d_in[17];
    const float* x2c_w   = (const float*)d_in[18];
    const float* x2c_b   = (const float*)d_in[19];
    const float* h2mod_w = (const float*)d_in[20];
    const float* h2mod_b = (const float*)d_in[21];
    const float* mfw     = (const float*)d_in[22];
    const float* mfb     = (const float*)d_in[23];

    float* out       = (float*)d_out;
    float* out_hact  = out;              // [B,H]
    float* out_cell  = out + BH;         // [B,H]
    float* out_hebb  = out + 2 * BH;     // [B,H,H]

    // 1) gates (bf16 tensor pipe) + hebb reduction (DRAM) in ONE launch
    k1<<<NGB + NRB, 256>>>(inputs, h0, hebb,
                           x2f_w, x2i_w, x2o_w, x2c_w,
                           h2f_w, h2i_w, h2o_w, w);

    // 2) cell / hactiv / m / ei
    k2<<<BSZ, HSIZE>>>(c0, alpha, x2f_b, h2f_b, x2i_b, h2i_b, x2o_b, h2o_b,
                       x2c_b, h2mod_w, h2mod_b, mfw, mfb, out_hact, out_cell);

    // 3) hebb update (268MB R + 268MB W streaming)
    int nblk = (BSZ * HSIZE * HSIZE / 4) / 1024;   // 16384
    k3<<<nblk, 256>>>((const float4*)hebb, h0, (float4*)out_hebb);
}